// round 14
// baseline (speedup 1.0000x reference)
#include <cuda_runtime.h>
#include <cuda_bf16.h>
#include <cuda_fp16.h>

#define Sdim 2048
#define Bdim 2
#define Edim 1024
#define Hn   16
#define HDdim 64
#define Mrows (Sdim*Bdim)   // 4096 token rows
#define NAELEM ((size_t)Mrows*Edim)   // 4M
#define NBELEM ((size_t)Edim*Edim)    // 1M

// ---------------- scratch (device globals: allocation-free) ----------------
// fp16 split QKV (written by projection epilogues), layout [b*H+h][s][d]
#define QKV_ELEMS ((size_t)Bdim*Hn*Sdim*HDdim)
__device__ __align__(16) __half g_Qh[QKV_ELEMS];
__device__ __align__(16) __half g_Ql[QKV_ELEMS];
__device__ __align__(16) __half g_Kh[QKV_ELEMS];
__device__ __align__(16) __half g_Kl[QKV_ELEMS];
__device__ __align__(16) __half g_Vh[QKV_ELEMS];
__device__ __align__(16) __half g_Vl[QKV_ELEMS];

// bf16 split A operands: [0]=query (later reused for ctx), [1]=key, [2]=value
__device__ __align__(16) __nv_bfloat16 g_ah[3][NAELEM];
__device__ __align__(16) __nv_bfloat16 g_al[3][NAELEM];
// bf16 split weights: 0=Wq 1=Wk 2=Wv 3=Wo
__device__ __align__(16) __nv_bfloat16 g_bh[4][NBELEM];
__device__ __align__(16) __nv_bfloat16 g_bl[4][NBELEM];

// ---------------- split helpers ----------------
__device__ __forceinline__ void split1(float x, __nv_bfloat16& h, __nv_bfloat16& l) {
    h = __float2bfloat16(x);
    l = __float2bfloat16(x - __bfloat162float(h));
}
__device__ __forceinline__ void split4(const float4 v, __nv_bfloat16* hi, __nv_bfloat16* lo) {
    __nv_bfloat16 h0,h1,h2,h3,l0,l1,l2,l3;
    split1(v.x,h0,l0); split1(v.y,h1,l1); split1(v.z,h2,l2); split1(v.w,h3,l3);
    __nv_bfloat162* ph = (__nv_bfloat162*)hi;
    ph[0] = __halves2bfloat162(h0,h1); ph[1] = __halves2bfloat162(h2,h3);
    __nv_bfloat162* pl = (__nv_bfloat162*)lo;
    pl[0] = __halves2bfloat162(l0,l1); pl[1] = __halves2bfloat162(l2,l3);
}

// One launch covers inputs (3 x 4M) then weights (4 x 1M). Each 1024-elem block
// lies entirely inside one region (all region sizes are multiples of 1024).
__global__ __launch_bounds__(256) void split_all(const float* __restrict__ q,
                                                 const float* __restrict__ k,
                                                 const float* __restrict__ v,
                                                 const float* __restrict__ wq,
                                                 const float* __restrict__ wk,
                                                 const float* __restrict__ wv,
                                                 const float* __restrict__ wo) {
    const size_t i = ((size_t)blockIdx.x * blockDim.x + threadIdx.x) * 4;
    if (i < 3*NAELEM) {
        const int t = (int)(i >> 22);              // NAELEM = 2^22
        const size_t off = i & (NAELEM - 1);
        const float* x = (t == 0) ? q : (t == 1) ? k : v;
        split4(*(const float4*)(x + off), &g_ah[t][off], &g_al[t][off]);
    } else {
        const size_t j = i - 3*NAELEM;
        const int t = (int)(j >> 20);              // NBELEM = 2^20
        const size_t off = j & (NBELEM - 1);
        const float* x = (t == 0) ? wq : (t == 1) ? wk : (t == 2) ? wv : wo;
        split4(*(const float4*)(x + off), &g_bh[t][off], &g_bl[t][off]);
    }
}

// ---------------- mma helpers ----------------
__device__ __forceinline__ void ldmat_x4(unsigned& r0, unsigned& r1, unsigned& r2,
                                         unsigned& r3, unsigned addr) {
    asm volatile("ldmatrix.sync.aligned.m8n8.x4.shared.b16 {%0,%1,%2,%3}, [%4];"
                 : "=r"(r0), "=r"(r1), "=r"(r2), "=r"(r3) : "r"(addr));
}
__device__ __forceinline__ void ldmat_x4_t(unsigned& r0, unsigned& r1, unsigned& r2,
                                           unsigned& r3, unsigned addr) {
    asm volatile("ldmatrix.sync.aligned.m8n8.x4.trans.shared.b16 {%0,%1,%2,%3}, [%4];"
                 : "=r"(r0), "=r"(r1), "=r"(r2), "=r"(r3) : "r"(addr));
}
__device__ __forceinline__ void ldmat_x2(unsigned& r0, unsigned& r1, unsigned addr) {
    asm volatile("ldmatrix.sync.aligned.m8n8.x2.shared.b16 {%0,%1}, [%2];"
                 : "=r"(r0), "=r"(r1) : "r"(addr));
}
__device__ __forceinline__ void mma_bf16(float* c, const unsigned* a, const unsigned* b) {
    asm volatile(
        "mma.sync.aligned.m16n8k16.row.col.f32.bf16.bf16.f32 "
        "{%0,%1,%2,%3}, {%4,%5,%6,%7}, {%8,%9}, {%0,%1,%2,%3};"
        : "+f"(c[0]), "+f"(c[1]), "+f"(c[2]), "+f"(c[3])
        : "r"(a[0]), "r"(a[1]), "r"(a[2]), "r"(a[3]), "r"(b[0]), "r"(b[1]));
}
__device__ __forceinline__ void mma_f16(float* c, const unsigned* a, const unsigned* b) {
    asm volatile(
        "mma.sync.aligned.m16n8k16.row.col.f32.f16.f16.f32 "
        "{%0,%1,%2,%3}, {%4,%5,%6,%7}, {%8,%9}, {%0,%1,%2,%3};"
        : "+f"(c[0]), "+f"(c[1]), "+f"(c[2]), "+f"(c[3])
        : "r"(a[0]), "r"(a[1]), "r"(a[2]), "r"(a[3]), "r"(b[0]), "r"(b[1]));
}
// f16 accumulator variant (possible 2x rate); C/D = 2 regs of f16x2
__device__ __forceinline__ void mma_f16acc(unsigned* c, const unsigned* a, const unsigned* b) {
    asm volatile(
        "mma.sync.aligned.m16n8k16.row.col.f16.f16.f16.f16 "
        "{%0,%1}, {%2,%3,%4,%5}, {%6,%7}, {%0,%1};"
        : "+r"(c[0]), "+r"(c[1])
        : "r"(a[0]), "r"(a[1]), "r"(a[2]), "r"(a[3]), "r"(b[0]), "r"(b[1]));
}
__device__ __forceinline__ unsigned hmul2u(unsigned x, unsigned s) {
    __half2 r = __hmul2(*reinterpret_cast<__half2*>(&x), *reinterpret_cast<__half2*>(&s));
    return *reinterpret_cast<unsigned*>(&r);
}
__device__ __forceinline__ void cp_async16(unsigned saddr, const void* gaddr) {
    asm volatile("cp.async.cg.shared.global [%0], [%1], 16;" :: "r"(saddr), "l"(gaddr));
}
__device__ __forceinline__ unsigned pack_hl(float x, float y, unsigned& lo) {
    __half hx = __float2half_rn(x), hy = __float2half_rn(y);
    __half lx = __float2half_rn(x - __half2float(hx));
    __half ly = __float2half_rn(y - __half2float(hy));
    lo = ((unsigned)__half_as_ushort(ly) << 16) | (unsigned)__half_as_ushort(lx);
    return ((unsigned)__half_as_ushort(hy) << 16) | (unsigned)__half_as_ushort(hx);
}
__device__ __forceinline__ unsigned pack_h(float x, float y) {
    __half hx = __float2half_rn(x), hy = __float2half_rn(y);
    return ((unsigned)__half_as_ushort(hy) << 16) | (unsigned)__half_as_ushort(hx);
}
__device__ __forceinline__ unsigned pack_bf(float x, float y, unsigned& lo) {
    __nv_bfloat16 hx = __float2bfloat16(x), hy = __float2bfloat16(y);
    __nv_bfloat16 lx = __float2bfloat16(x - __bfloat162float(hx));
    __nv_bfloat16 ly = __float2bfloat16(y - __bfloat162float(hy));
    lo = ((unsigned)__bfloat16_as_ushort(ly) << 16) | (unsigned)__bfloat16_as_ushort(lx);
    return ((unsigned)__bfloat16_as_ushort(hy) << 16) | (unsigned)__bfloat16_as_ushort(hx);
}

// ---------------- tensor-core GEMM: C[4096,1024] = A @ B^T + bias ----------------
// 128x128 CTA tile, 8 warps (2m x 4n), K-block 32, 2-stage cp.async, 2 CTAs/SM.
// One barrier per K-block: wait; sync; issue next load; compute.
// MODE 0: fused QKV (grid.z selects operands; epilogue -> fp16 hi/lo head-major)
// MODE 1: output projection (ctx split @ g_ah[0] x Wo split; epilogue -> fp32 out)
#define PITCH 40
#define KBLK  32
#define MAT_BYTES (128*PITCH*2)
#define STAGE_BYTES (4*MAT_BYTES)       // 40960
#define GEMM_SMEM (2*STAGE_BYTES)       // 81920 -> 2 CTAs/SM
#define NKB (Edim/KBLK)                 // 32

template<int MODE>
__global__ __launch_bounds__(256, 2) void gemm_tc(const float* __restrict__ bias0,
                                                  const float* __restrict__ bias1,
                                                  const float* __restrict__ bias2,
                                                  float* __restrict__ out) {
    extern __shared__ char smc[];
    const unsigned sbase = (unsigned)__cvta_generic_to_shared(smc);
    const int tid = threadIdx.x, lane = tid & 31, wid = tid >> 5;
    const int m0 = blockIdx.y << 7, n0 = blockIdx.x << 7;
    const int z = (MODE == 0) ? blockIdx.z : 0;
    const int wm = (wid & 1) << 6;
    const int wn = (wid >> 1) << 5;

    const __nv_bfloat16* Ah = (MODE == 0) ? g_ah[z] : g_ah[0];
    const __nv_bfloat16* Al = (MODE == 0) ? g_al[z] : g_al[0];
    const __nv_bfloat16* Bh = (MODE == 0) ? g_bh[z] : g_bh[3];
    const __nv_bfloat16* Bl = (MODE == 0) ? g_bl[z] : g_bl[3];
    const float* bias = (MODE == 1) ? bias0
                       : (z == 0) ? bias0 : (z == 1) ? bias1 : bias2;

    unsigned soff[8]; const __nv_bfloat16* gp[8];
#pragma unroll
    for (int u = 0; u < 8; u++) {
        const int i = u*256 + tid;
        const int mat = i >> 9;
        const int row = (i >> 2) & 127, c4 = i & 3;
        soff[u] = mat*MAT_BYTES + row*(PITCH*2) + c4*16;
        const __nv_bfloat16* src = (mat==0) ? Ah : (mat==1) ? Al : (mat==2) ? Bh : Bl;
        const size_t r = (mat < 2) ? (size_t)(m0 + row) : (size_t)(n0 + row);
        gp[u] = src + r*Edim + c4*8;
    }
    auto load_stage = [&](int kb) {
        const unsigned sb = sbase + (kb & 1)*STAGE_BYTES;
#pragma unroll
        for (int u = 0; u < 8; u++) cp_async16(sb + soff[u], gp[u] + kb*KBLK);
        asm volatile("cp.async.commit_group;");
    };

    float c[4][4][4] = {};
    load_stage(0);

    for (int kb = 0; kb < NKB; kb++) {
        asm volatile("cp.async.wait_group 0;");   // stage kb resident
        __syncthreads();                          // and prior compute done with other stage
        if (kb + 1 < NKB) load_stage(kb + 1);     // overlaps compute below

        const unsigned sAh = sbase + (kb & 1)*STAGE_BYTES;
        const unsigned sAl = sAh + MAT_BYTES;
        const unsigned sBh = sAh + 2*MAT_BYTES;
        const unsigned sBl = sAh + 3*MAT_BYTES;
        const int arow = wm + (lane & 15);
        const int akof = (lane >> 4) << 3;
        const int brow = wn + (lane & 7);
        const int bkof = ((lane >> 3) & 1) << 3;

#pragma unroll
        for (int ks = 0; ks < 2; ks++) {
            const int k0 = ks << 4;
            unsigned ah[4][4], al[4][4], b[4][2];
#pragma unroll
            for (int mf = 0; mf < 4; mf++) {
                const unsigned off = (unsigned)(arow + mf*16)*(PITCH*2) + (k0 + akof)*2;
                ldmat_x4(ah[mf][0], ah[mf][1], ah[mf][2], ah[mf][3], sAh + off);
                ldmat_x4(al[mf][0], al[mf][1], al[mf][2], al[mf][3], sAl + off);
            }
#pragma unroll
            for (int nf = 0; nf < 4; nf++) {
                const unsigned off = (unsigned)(brow + nf*8)*(PITCH*2) + (k0 + bkof)*2;
                ldmat_x2(b[nf][0], b[nf][1], sBh + off);
            }
#pragma unroll
            for (int mf = 0; mf < 4; mf++)
#pragma unroll
                for (int nf = 0; nf < 4; nf++) {
                    mma_bf16(c[mf][nf], ah[mf], b[nf]);
                    mma_bf16(c[mf][nf], al[mf], b[nf]);
                }
#pragma unroll
            for (int nf = 0; nf < 4; nf++) {
                const unsigned off = (unsigned)(brow + nf*8)*(PITCH*2) + (k0 + bkof)*2;
                ldmat_x2(b[nf][0], b[nf][1], sBl + off);
            }
#pragma unroll
            for (int mf = 0; mf < 4; mf++)
#pragma unroll
                for (int nf = 0; nf < 4; nf++)
                    mma_bf16(c[mf][nf], ah[mf], b[nf]);
        }
    }

    // epilogue
    const int g = lane >> 2, tig = lane & 3;
#pragma unroll
    for (int mf = 0; mf < 4; mf++) {
#pragma unroll
        for (int nf = 0; nf < 4; nf++) {
            const int col = n0 + wn + nf*8 + tig*2;
            const float2 bb = *(const float2*)(bias + col);
#pragma unroll
            for (int half = 0; half < 2; half++) {
                const int m = m0 + wm + mf*16 + g + half*8;
                float2 o;
                o.x = c[mf][nf][half*2+0] + bb.x;
                o.y = c[mf][nf][half*2+1] + bb.y;
                if (MODE == 1) {
                    *(float2*)(out + (size_t)m * Edim + col) = o;
                } else {
                    const int s = m >> 1, b2 = m & 1;   // m = s*B + b
                    const int hh = col >> 6, d2 = col & 63;
                    const size_t idx = ((size_t)(b2*Hn + hh) * Sdim + s) * HDdim + d2;
                    unsigned lo;
                    const unsigned hi = pack_hl(o.x, o.y, lo);
                    __half* dh = (z == 0) ? g_Qh : (z == 1) ? g_Kh : g_Vh;
                    __half* dl = (z == 0) ? g_Ql : (z == 1) ? g_Kl : g_Vl;
                    *(unsigned*)(dh + idx) = hi;
                    *(unsigned*)(dl + idx) = lo;
                }
            }
        }
    }
}

// ---------------- tensor-core flash attention ----------------
// BLOCK_M=128 (8 warps x m16), BLOCK_N=64 keys/tile, HD=64.
// QK = QhKh + QhKl + QlKh (3 products, f32 accum).
// PV = PhVh (f32 accum) + PhVl (f16 accum probe — possible 2x rate; cross term
// is ~2^-11 of O so f16 accumulation error ~2.5e-7 absolute).
// KV stage 1 overlays the Q smem region -> 72KB smem, 2 CTAs/SM.
// Epilogue merges f16 cross accum and writes bf16 (hi,lo) ctx split.
#define FPITCH_B 144
#define QSM_BYTES (2*128*FPITCH_B)      // 36864 (also stage-1 KV region)
#define KSTAGE_BYTES (4*64*FPITCH_B)    // 36864
#define FL_SMEM (QSM_BYTES + KSTAGE_BYTES)   // 73728
#define NTILES (Sdim/64)

__global__ __launch_bounds__(256, 2) void flash_tc() {
    extern __shared__ char smc[];
    const unsigned sbase = (unsigned)__cvta_generic_to_shared(smc);
    const unsigned sQ = sbase;                    // Q region; later KV stage 1
    const unsigned sKV = sbase + QSM_BYTES;       // KV stage 0
    const int tid = threadIdx.x, lane = tid & 31, wid = tid >> 5;
    const int bh = blockIdx.y;
    const int q0 = blockIdx.x << 7;
    const int wm = wid << 4;

    const size_t qbase = ((size_t)bh * Sdim + q0) * HDdim;
    const size_t kbase = (size_t)bh * Sdim * HDdim;

#pragma unroll
    for (int u = 0; u < 8; u++) {
        const int i = u*256 + tid;
        const int mat = i >> 10, row = (i >> 3) & 127, c8 = i & 7;
        const __half* src = (mat ? g_Ql : g_Qh) + qbase + (size_t)row*HDdim + c8*8;
        cp_async16(sQ + mat*(128*FPITCH_B) + row*FPITCH_B + c8*16, src);
    }
    auto load_kv = [&](int kt, unsigned sb) {
#pragma unroll
        for (int u = 0; u < 8; u++) {
            const int i = u*256 + tid;
            const int mat = i >> 9, row = (i >> 3) & 63, c8 = i & 7;
            const __half* src = (mat==0 ? g_Kh : mat==1 ? g_Kl : mat==2 ? g_Vh : g_Vl)
                              + kbase + (size_t)(kt*64 + row)*HDdim + c8*8;
            cp_async16(sb + mat*(64*FPITCH_B) + row*FPITCH_B + c8*16, src);
        }
        asm volatile("cp.async.commit_group;");
    };
    load_kv(0, sKV);   // one group: Q chunks + KV tile 0

    asm volatile("cp.async.wait_group 0;");
    __syncthreads();

    // Q A-fragments, loaded once; afterwards the Q region becomes KV stage 1
    unsigned qh[4][4], ql[4][4];
    {
        const unsigned aoff = (unsigned)(wm + (lane & 15))*FPITCH_B + ((lane >> 4) << 3)*2;
#pragma unroll
        for (int kf = 0; kf < 4; kf++) {
            ldmat_x4(qh[kf][0], qh[kf][1], qh[kf][2], qh[kf][3], sQ + aoff + kf*32);
            ldmat_x4(ql[kf][0], ql[kf][1], ql[kf][2], ql[kf][3],
                     sQ + 128*FPITCH_B + aoff + kf*32);
        }
    }
    __syncthreads();               // all warps done reading Q region
    load_kv(1, sQ);                // prefetch tile 1 into the freed Q region

    float acc[8][4] = {};
    unsigned o16[8][2] = {};       // f16x2 cross-term accumulators (Ph*Vl)
    float mr0 = -1e30f, mr1 = -1e30f, lr0 = 0.f, lr1 = 0.f;

    for (int kt = 0; kt < NTILES; kt++) {
        if (kt) {
            asm volatile("cp.async.wait_group 0;");
            __syncthreads();
            if (kt + 1 < NTILES) load_kv(kt + 1, (kt & 1) ? sKV : sQ);
        }
        const unsigned kb = (kt & 1) ? sQ : sKV;

        // ---- S = Q @ K^T  (3 products) ----
        float s[8][4] = {};
        {
            const int krow = ((lane >> 4) & 1)*8 + (lane & 7);
            const int ksel = ((lane >> 3) & 1)*8;
#pragma unroll
            for (int kf = 0; kf < 4; kf++) {
                const unsigned coff = (unsigned)(kf*16 + ksel)*2;
#pragma unroll
                for (int np = 0; np < 4; np++) {
                    unsigned bhf[4], blf[4];
                    const unsigned ad = kb + (unsigned)(np*16 + krow)*FPITCH_B + coff;
                    ldmat_x4(bhf[0], bhf[1], bhf[2], bhf[3], ad);
                    ldmat_x4(blf[0], blf[1], blf[2], blf[3], ad + 64*FPITCH_B);
                    mma_f16(s[2*np],   qh[kf], &bhf[0]);
                    mma_f16(s[2*np+1], qh[kf], &bhf[2]);
                    mma_f16(s[2*np],   qh[kf], &blf[0]);
                    mma_f16(s[2*np+1], qh[kf], &blf[2]);
                    mma_f16(s[2*np],   ql[kf], &bhf[0]);
                    mma_f16(s[2*np+1], ql[kf], &bhf[2]);
                }
            }
        }

        // ---- online softmax ----
#pragma unroll
        for (int rh = 0; rh < 2; rh++) {
            const int i0 = rh*2;
            float mx = fmaxf(s[0][i0], s[0][i0+1]);
#pragma unroll
            for (int nf = 1; nf < 8; nf++)
                mx = fmaxf(mx, fmaxf(s[nf][i0], s[nf][i0+1]));
            mx = fmaxf(mx, __shfl_xor_sync(0xffffffffu, mx, 1));
            mx = fmaxf(mx, __shfl_xor_sync(0xffffffffu, mx, 2));
            const float mold = rh ? mr1 : mr0;
            const float mnew = fmaxf(mold, mx);
            const float alpha = __expf(mold - mnew);
            float rs = 0.f;
#pragma unroll
            for (int nf = 0; nf < 8; nf++) {
                s[nf][i0]   = __expf(s[nf][i0]   - mnew);
                s[nf][i0+1] = __expf(s[nf][i0+1] - mnew);
                rs += s[nf][i0] + s[nf][i0+1];
            }
            rs += __shfl_xor_sync(0xffffffffu, rs, 1);
            rs += __shfl_xor_sync(0xffffffffu, rs, 2);
            if (rh) { lr1 = lr1*alpha + rs; mr1 = mnew; }
            else    { lr0 = lr0*alpha + rs; mr0 = mnew; }
            // rescale f32 accum + f16 cross accum for this row half
            const __half2 ha2 = __float2half2_rn(alpha);
            const unsigned hau = *reinterpret_cast<const unsigned*>(&ha2);
#pragma unroll
            for (int nf = 0; nf < 8; nf++) {
                acc[nf][i0]   *= alpha;
                acc[nf][i0+1] *= alpha;
                o16[nf][rh] = hmul2u(o16[nf][rh], hau);
            }
        }

        // ---- P -> fp16 A-fragments (hi only) ----
        unsigned pa[4][4];
#pragma unroll
        for (int kf = 0; kf < 4; kf++) {
            pa[kf][0] = pack_h(s[2*kf][0],   s[2*kf][1]);
            pa[kf][1] = pack_h(s[2*kf][2],   s[2*kf][3]);
            pa[kf][2] = pack_h(s[2*kf+1][0], s[2*kf+1][1]);
            pa[kf][3] = pack_h(s[2*kf+1][2], s[2*kf+1][3]);
        }

        // ---- O += P @ V: Ph*Vh (f32 acc) + Ph*Vl (f16 acc) ----
        {
            const int vrow = lane & 15;
            const int vsel = ((lane >> 4) & 1)*8;
#pragma unroll
            for (int kf = 0; kf < 4; kf++) {
#pragma unroll
                for (int np = 0; np < 4; np++) {
                    unsigned vhf[4], vlf[4];
                    const unsigned ad = kb + 2*(64*FPITCH_B)
                        + (unsigned)(kf*16 + vrow)*FPITCH_B + (np*16 + vsel)*2;
                    ldmat_x4_t(vhf[0], vhf[1], vhf[2], vhf[3], ad);
                    ldmat_x4_t(vlf[0], vlf[1], vlf[2], vlf[3], ad + 64*FPITCH_B);
                    mma_f16(acc[2*np],   pa[kf], &vhf[0]);
                    mma_f16(acc[2*np+1], pa[kf], &vhf[2]);
                    // cross term: f16 accumulators. o16[nf][0] covers acc[nf][0..1]
                    // (rows g), o16[nf][1] covers acc[nf][2..3] (rows g+8).
                    {
                        unsigned ctmp0[2] = { o16[2*np][0],   o16[2*np][1] };
                        unsigned ctmp1[2] = { o16[2*np+1][0], o16[2*np+1][1] };
                        mma_f16acc(ctmp0, pa[kf], &vlf[0]);
                        mma_f16acc(ctmp1, pa[kf], &vlf[2]);
                        o16[2*np][0] = ctmp0[0];   o16[2*np][1] = ctmp0[1];
                        o16[2*np+1][0] = ctmp1[0]; o16[2*np+1][1] = ctmp1[1];
                    }
                }
            }
        }
    }

    // epilogue -> bf16 (hi,lo) ctx split at g_ah[0]/g_al[0], layout [s*B+b][E]
    const int b = bh >> 4, hh = bh & 15;
    const int g = lane >> 2, tig = lane & 3;
    const float inv0 = 1.0f / lr0, inv1 = 1.0f / lr1;
    const int sg = q0 + wm + g;
#pragma unroll
    for (int nf = 0; nf < 8; nf++) {
        const int d = nf*8 + tig*2;
        const size_t i0 = ((size_t)sg*Bdim + b)*Edim + hh*HDdim + d;
        const size_t i1 = ((size_t)(sg+8)*Bdim + b)*Edim + hh*HDdim + d;
        const __half2 x0 = *reinterpret_cast<const __half2*>(&o16[nf][0]);
        const __half2 x1 = *reinterpret_cast<const __half2*>(&o16[nf][1]);
        unsigned lo0, lo1;
        const unsigned hi0 = pack_bf((acc[nf][0] + __low2float(x0))*inv0,
                                     (acc[nf][1] + __high2float(x0))*inv0, lo0);
        const unsigned hi1 = pack_bf((acc[nf][2] + __low2float(x1))*inv1,
                                     (acc[nf][3] + __high2float(x1))*inv1, lo1);
        *(unsigned*)(&g_ah[0][i0]) = hi0;
        *(unsigned*)(&g_al[0][i0]) = lo0;
        *(unsigned*)(&g_ah[0][i1]) = hi1;
        *(unsigned*)(&g_al[0][i1]) = lo1;
    }
}

// ---------------- launch ----------------
extern "C" void kernel_launch(void* const* d_in, const int* in_sizes, int n_in,
                              void* d_out, int out_size) {
    const float* query = (const float*)d_in[0];
    const float* key_  = (const float*)d_in[1];
    const float* value = (const float*)d_in[2];
    const float* Wq = (const float*)d_in[3];
    const float* bq = (const float*)d_in[4];
    const float* Wk = (const float*)d_in[5];
    const float* bk = (const float*)d_in[6];
    const float* Wv = (const float*)d_in[7];
    const float* bv = (const float*)d_in[8];
    const float* Wo = (const float*)d_in[9];
    const float* bo = (const float*)d_in[10];
    float* out = (float*)d_out;

    static bool attr_set = false;
    if (!attr_set) {
        cudaFuncSetAttribute(flash_tc, cudaFuncAttributeMaxDynamicSharedMemorySize, FL_SMEM);
        cudaFuncSetAttribute(gemm_tc<0>, cudaFuncAttributeMaxDynamicSharedMemorySize, GEMM_SMEM);
        cudaFuncSetAttribute(gemm_tc<1>, cudaFuncAttributeMaxDynamicSharedMemorySize, GEMM_SMEM);
        attr_set = true;
    }

    const unsigned nsplit = (unsigned)((3*NAELEM + 4*NBELEM) / 1024);   // 16384
    split_all<<<nsplit, 256>>>(query, key_, value, Wq, Wk, Wv, Wo);

    gemm_tc<0><<<dim3(Edim/128, Mrows/128, 3), 256, GEMM_SMEM>>>(bq, bk, bv, nullptr);

    flash_tc<<<dim3(Sdim/128, Bdim*Hn), 256, FL_SMEM>>>();

    gemm_tc<1><<<dim3(Edim/128, Mrows/128), 256, GEMM_SMEM>>>(bo, nullptr, nullptr, out);
}

// round 15
// speedup vs baseline: 1.0027x; 1.0027x over previous
#include <cuda_runtime.h>
#include <cuda_bf16.h>
#include <cuda_fp16.h>

#define Sdim 2048
#define Bdim 2
#define Edim 1024
#define Hn   16
#define HDdim 64
#define Mrows (Sdim*Bdim)   // 4096 token rows
#define NAELEM ((size_t)Mrows*Edim)   // 4M
#define NBELEM ((size_t)Edim*Edim)    // 1M

// ---------------- scratch (device globals: allocation-free) ----------------
// fp16 split QKV (written by projection epilogues), layout [b*H+h][s][d]
#define QKV_ELEMS ((size_t)Bdim*Hn*Sdim*HDdim)
__device__ __align__(16) __half g_Qh[QKV_ELEMS];
__device__ __align__(16) __half g_Ql[QKV_ELEMS];
__device__ __align__(16) __half g_Kh[QKV_ELEMS];
__device__ __align__(16) __half g_Kl[QKV_ELEMS];
__device__ __align__(16) __half g_Vh[QKV_ELEMS];
__device__ __align__(16) __half g_Vl[QKV_ELEMS];

// bf16 split A operands: [0]=query (later reused for ctx), [1]=key, [2]=value
__device__ __align__(16) __nv_bfloat16 g_ah[3][NAELEM];
__device__ __align__(16) __nv_bfloat16 g_al[3][NAELEM];
// bf16 split weights: 0=Wq 1=Wk 2=Wv 3=Wo
__device__ __align__(16) __nv_bfloat16 g_bh[4][NBELEM];
__device__ __align__(16) __nv_bfloat16 g_bl[4][NBELEM];

// ---------------- split helpers ----------------
__device__ __forceinline__ void split1(float x, __nv_bfloat16& h, __nv_bfloat16& l) {
    h = __float2bfloat16(x);
    l = __float2bfloat16(x - __bfloat162float(h));
}
__device__ __forceinline__ void split4(const float4 v, __nv_bfloat16* hi, __nv_bfloat16* lo) {
    __nv_bfloat16 h0,h1,h2,h3,l0,l1,l2,l3;
    split1(v.x,h0,l0); split1(v.y,h1,l1); split1(v.z,h2,l2); split1(v.w,h3,l3);
    __nv_bfloat162* ph = (__nv_bfloat162*)hi;
    ph[0] = __halves2bfloat162(h0,h1); ph[1] = __halves2bfloat162(h2,h3);
    __nv_bfloat162* pl = (__nv_bfloat162*)lo;
    pl[0] = __halves2bfloat162(l0,l1); pl[1] = __halves2bfloat162(l2,l3);
}

// One launch covers inputs (3 x 4M) then weights (4 x 1M). Each 1024-elem block
// lies entirely inside one region (all region sizes are multiples of 1024).
__global__ __launch_bounds__(256) void split_all(const float* __restrict__ q,
                                                 const float* __restrict__ k,
                                                 const float* __restrict__ v,
                                                 const float* __restrict__ wq,
                                                 const float* __restrict__ wk,
                                                 const float* __restrict__ wv,
                                                 const float* __restrict__ wo) {
    const size_t i = ((size_t)blockIdx.x * blockDim.x + threadIdx.x) * 4;
    if (i < 3*NAELEM) {
        const int t = (int)(i >> 22);              // NAELEM = 2^22
        const size_t off = i & (NAELEM - 1);
        const float* x = (t == 0) ? q : (t == 1) ? k : v;
        split4(*(const float4*)(x + off), &g_ah[t][off], &g_al[t][off]);
    } else {
        const size_t j = i - 3*NAELEM;
        const int t = (int)(j >> 20);              // NBELEM = 2^20
        const size_t off = j & (NBELEM - 1);
        const float* x = (t == 0) ? wq : (t == 1) ? wk : (t == 2) ? wv : wo;
        split4(*(const float4*)(x + off), &g_bh[t][off], &g_bl[t][off]);
    }
}

// ---------------- mma helpers ----------------
__device__ __forceinline__ void ldmat_x4(unsigned& r0, unsigned& r1, unsigned& r2,
                                         unsigned& r3, unsigned addr) {
    asm volatile("ldmatrix.sync.aligned.m8n8.x4.shared.b16 {%0,%1,%2,%3}, [%4];"
                 : "=r"(r0), "=r"(r1), "=r"(r2), "=r"(r3) : "r"(addr));
}
__device__ __forceinline__ void ldmat_x4_t(unsigned& r0, unsigned& r1, unsigned& r2,
                                           unsigned& r3, unsigned addr) {
    asm volatile("ldmatrix.sync.aligned.m8n8.x4.trans.shared.b16 {%0,%1,%2,%3}, [%4];"
                 : "=r"(r0), "=r"(r1), "=r"(r2), "=r"(r3) : "r"(addr));
}
__device__ __forceinline__ void ldmat_x2(unsigned& r0, unsigned& r1, unsigned addr) {
    asm volatile("ldmatrix.sync.aligned.m8n8.x2.shared.b16 {%0,%1}, [%2];"
                 : "=r"(r0), "=r"(r1) : "r"(addr));
}
__device__ __forceinline__ void mma_bf16(float* c, const unsigned* a, const unsigned* b) {
    asm volatile(
        "mma.sync.aligned.m16n8k16.row.col.f32.bf16.bf16.f32 "
        "{%0,%1,%2,%3}, {%4,%5,%6,%7}, {%8,%9}, {%0,%1,%2,%3};"
        : "+f"(c[0]), "+f"(c[1]), "+f"(c[2]), "+f"(c[3])
        : "r"(a[0]), "r"(a[1]), "r"(a[2]), "r"(a[3]), "r"(b[0]), "r"(b[1]));
}
__device__ __forceinline__ void mma_f16(float* c, const unsigned* a, const unsigned* b) {
    asm volatile(
        "mma.sync.aligned.m16n8k16.row.col.f32.f16.f16.f32 "
        "{%0,%1,%2,%3}, {%4,%5,%6,%7}, {%8,%9}, {%0,%1,%2,%3};"
        : "+f"(c[0]), "+f"(c[1]), "+f"(c[2]), "+f"(c[3])
        : "r"(a[0]), "r"(a[1]), "r"(a[2]), "r"(a[3]), "r"(b[0]), "r"(b[1]));
}
// f16 accumulator variant (possible 2x rate); C/D = 2 regs of f16x2
__device__ __forceinline__ void mma_f16acc(unsigned* c, const unsigned* a, const unsigned* b) {
    asm volatile(
        "mma.sync.aligned.m16n8k16.row.col.f16.f16.f16.f16 "
        "{%0,%1}, {%2,%3,%4,%5}, {%6,%7}, {%0,%1};"
        : "+r"(c[0]), "+r"(c[1])
        : "r"(a[0]), "r"(a[1]), "r"(a[2]), "r"(a[3]), "r"(b[0]), "r"(b[1]));
}
__device__ __forceinline__ unsigned hmul2u(unsigned x, unsigned s) {
    __half2 r = __hmul2(*reinterpret_cast<__half2*>(&x), *reinterpret_cast<__half2*>(&s));
    return *reinterpret_cast<unsigned*>(&r);
}
__device__ __forceinline__ void cp_async16(unsigned saddr, const void* gaddr) {
    asm volatile("cp.async.cg.shared.global [%0], [%1], 16;" :: "r"(saddr), "l"(gaddr));
}
__device__ __forceinline__ unsigned pack_hl(float x, float y, unsigned& lo) {
    __half hx = __float2half_rn(x), hy = __float2half_rn(y);
    __half lx = __float2half_rn(x - __half2float(hx));
    __half ly = __float2half_rn(y - __half2float(hy));
    lo = ((unsigned)__half_as_ushort(ly) << 16) | (unsigned)__half_as_ushort(lx);
    return ((unsigned)__half_as_ushort(hy) << 16) | (unsigned)__half_as_ushort(hx);
}
__device__ __forceinline__ unsigned pack_h(float x, float y) {
    __half hx = __float2half_rn(x), hy = __float2half_rn(y);
    return ((unsigned)__half_as_ushort(hy) << 16) | (unsigned)__half_as_ushort(hx);
}
__device__ __forceinline__ unsigned pack_bf(float x, float y, unsigned& lo) {
    __nv_bfloat16 hx = __float2bfloat16(x), hy = __float2bfloat16(y);
    __nv_bfloat16 lx = __float2bfloat16(x - __bfloat162float(hx));
    __nv_bfloat16 ly = __float2bfloat16(y - __bfloat162float(hy));
    lo = ((unsigned)__bfloat16_as_ushort(ly) << 16) | (unsigned)__bfloat16_as_ushort(lx);
    return ((unsigned)__bfloat16_as_ushort(hy) << 16) | (unsigned)__bfloat16_as_ushort(hx);
}

// ---------------- tensor-core GEMM: C[4096,1024] = A @ B^T + bias ----------------
// 128x128 CTA tile, 8 warps (2m x 4n), K-block 32, 2-stage cp.async, 2 CTAs/SM.
// One barrier per K-block: wait; sync; issue next load; compute.
// MODE 0: fused QKV (grid.z selects operands; epilogue -> fp16 hi/lo head-major)
// MODE 1: output projection (ctx split @ g_ah[0] x Wo split; epilogue -> fp32 out)
#define PITCH 40
#define KBLK  32
#define MAT_BYTES (128*PITCH*2)
#define STAGE_BYTES (4*MAT_BYTES)       // 40960
#define GEMM_SMEM (2*STAGE_BYTES)       // 81920 -> 2 CTAs/SM
#define NKB (Edim/KBLK)                 // 32

template<int MODE>
__global__ __launch_bounds__(256, 2) void gemm_tc(const float* __restrict__ bias0,
                                                  const float* __restrict__ bias1,
                                                  const float* __restrict__ bias2,
                                                  float* __restrict__ out) {
    extern __shared__ char smc[];
    const unsigned sbase = (unsigned)__cvta_generic_to_shared(smc);
    const int tid = threadIdx.x, lane = tid & 31, wid = tid >> 5;
    const int m0 = blockIdx.y << 7, n0 = blockIdx.x << 7;
    const int z = (MODE == 0) ? blockIdx.z : 0;
    const int wm = (wid & 1) << 6;
    const int wn = (wid >> 1) << 5;

    const __nv_bfloat16* Ah = (MODE == 0) ? g_ah[z] : g_ah[0];
    const __nv_bfloat16* Al = (MODE == 0) ? g_al[z] : g_al[0];
    const __nv_bfloat16* Bh = (MODE == 0) ? g_bh[z] : g_bh[3];
    const __nv_bfloat16* Bl = (MODE == 0) ? g_bl[z] : g_bl[3];
    const float* bias = (MODE == 1) ? bias0
                       : (z == 0) ? bias0 : (z == 1) ? bias1 : bias2;

    unsigned soff[8]; const __nv_bfloat16* gp[8];
#pragma unroll
    for (int u = 0; u < 8; u++) {
        const int i = u*256 + tid;
        const int mat = i >> 9;
        const int row = (i >> 2) & 127, c4 = i & 3;
        soff[u] = mat*MAT_BYTES + row*(PITCH*2) + c4*16;
        const __nv_bfloat16* src = (mat==0) ? Ah : (mat==1) ? Al : (mat==2) ? Bh : Bl;
        const size_t r = (mat < 2) ? (size_t)(m0 + row) : (size_t)(n0 + row);
        gp[u] = src + r*Edim + c4*8;
    }
    auto load_stage = [&](int kb) {
        const unsigned sb = sbase + (kb & 1)*STAGE_BYTES;
#pragma unroll
        for (int u = 0; u < 8; u++) cp_async16(sb + soff[u], gp[u] + kb*KBLK);
        asm volatile("cp.async.commit_group;");
    };

    float c[4][4][4] = {};
    load_stage(0);

    for (int kb = 0; kb < NKB; kb++) {
        asm volatile("cp.async.wait_group 0;");   // stage kb resident
        __syncthreads();                          // and prior compute done with other stage
        if (kb + 1 < NKB) load_stage(kb + 1);     // overlaps compute below

        const unsigned sAh = sbase + (kb & 1)*STAGE_BYTES;
        const unsigned sAl = sAh + MAT_BYTES;
        const unsigned sBh = sAh + 2*MAT_BYTES;
        const unsigned sBl = sAh + 3*MAT_BYTES;
        const int arow = wm + (lane & 15);
        const int akof = (lane >> 4) << 3;
        const int brow = wn + (lane & 7);
        const int bkof = ((lane >> 3) & 1) << 3;

#pragma unroll
        for (int ks = 0; ks < 2; ks++) {
            const int k0 = ks << 4;
            unsigned ah[4][4], al[4][4], b[4][2];
#pragma unroll
            for (int mf = 0; mf < 4; mf++) {
                const unsigned off = (unsigned)(arow + mf*16)*(PITCH*2) + (k0 + akof)*2;
                ldmat_x4(ah[mf][0], ah[mf][1], ah[mf][2], ah[mf][3], sAh + off);
                ldmat_x4(al[mf][0], al[mf][1], al[mf][2], al[mf][3], sAl + off);
            }
#pragma unroll
            for (int nf = 0; nf < 4; nf++) {
                const unsigned off = (unsigned)(brow + nf*8)*(PITCH*2) + (k0 + bkof)*2;
                ldmat_x2(b[nf][0], b[nf][1], sBh + off);
            }
#pragma unroll
            for (int mf = 0; mf < 4; mf++)
#pragma unroll
                for (int nf = 0; nf < 4; nf++) {
                    mma_bf16(c[mf][nf], ah[mf], b[nf]);
                    mma_bf16(c[mf][nf], al[mf], b[nf]);
                }
#pragma unroll
            for (int nf = 0; nf < 4; nf++) {
                const unsigned off = (unsigned)(brow + nf*8)*(PITCH*2) + (k0 + bkof)*2;
                ldmat_x2(b[nf][0], b[nf][1], sBl + off);
            }
#pragma unroll
            for (int mf = 0; mf < 4; mf++)
#pragma unroll
                for (int nf = 0; nf < 4; nf++)
                    mma_bf16(c[mf][nf], ah[mf], b[nf]);
        }
    }

    // epilogue
    const int g = lane >> 2, tig = lane & 3;
#pragma unroll
    for (int mf = 0; mf < 4; mf++) {
#pragma unroll
        for (int nf = 0; nf < 4; nf++) {
            const int col = n0 + wn + nf*8 + tig*2;
            const float2 bb = *(const float2*)(bias + col);
#pragma unroll
            for (int half = 0; half < 2; half++) {
                const int m = m0 + wm + mf*16 + g + half*8;
                float2 o;
                o.x = c[mf][nf][half*2+0] + bb.x;
                o.y = c[mf][nf][half*2+1] + bb.y;
                if (MODE == 1) {
                    *(float2*)(out + (size_t)m * Edim + col) = o;
                } else {
                    const int s = m >> 1, b2 = m & 1;   // m = s*B + b
                    const int hh = col >> 6, d2 = col & 63;
                    const size_t idx = ((size_t)(b2*Hn + hh) * Sdim + s) * HDdim + d2;
                    unsigned lo;
                    const unsigned hi = pack_hl(o.x, o.y, lo);
                    __half* dh = (z == 0) ? g_Qh : (z == 1) ? g_Kh : g_Vh;
                    __half* dl = (z == 0) ? g_Ql : (z == 1) ? g_Kl : g_Vl;
                    *(unsigned*)(dh + idx) = hi;
                    *(unsigned*)(dl + idx) = lo;
                }
            }
        }
    }
}

// ---------------- tensor-core flash attention ----------------
// BLOCK_M=128 (8 warps x m16), BLOCK_N=64 keys/tile, HD=64.
// QK = QhKh + QhKl + QlKh (3 products, f32 accum).
// PV = PhVh (f32 accum) + PhVl (f16 accum probe — possible 2x rate; cross term
// is ~2^-11 of O so f16 accumulation error ~2.5e-7 absolute).
// KV stage 1 overlays the Q smem region -> 72KB smem, 2 CTAs/SM.
// Epilogue merges f16 cross accum and writes bf16 (hi,lo) ctx split.
#define FPITCH_B 144
#define QSM_BYTES (2*128*FPITCH_B)      // 36864 (also stage-1 KV region)
#define KSTAGE_BYTES (4*64*FPITCH_B)    // 36864
#define FL_SMEM (QSM_BYTES + KSTAGE_BYTES)   // 73728
#define NTILES (Sdim/64)

__global__ __launch_bounds__(256, 2) void flash_tc() {
    extern __shared__ char smc[];
    const unsigned sbase = (unsigned)__cvta_generic_to_shared(smc);
    const unsigned sQ = sbase;                    // Q region; later KV stage 1
    const unsigned sKV = sbase + QSM_BYTES;       // KV stage 0
    const int tid = threadIdx.x, lane = tid & 31, wid = tid >> 5;
    const int bh = blockIdx.y;
    const int q0 = blockIdx.x << 7;
    const int wm = wid << 4;

    const size_t qbase = ((size_t)bh * Sdim + q0) * HDdim;
    const size_t kbase = (size_t)bh * Sdim * HDdim;

#pragma unroll
    for (int u = 0; u < 8; u++) {
        const int i = u*256 + tid;
        const int mat = i >> 10, row = (i >> 3) & 127, c8 = i & 7;
        const __half* src = (mat ? g_Ql : g_Qh) + qbase + (size_t)row*HDdim + c8*8;
        cp_async16(sQ + mat*(128*FPITCH_B) + row*FPITCH_B + c8*16, src);
    }
    auto load_kv = [&](int kt, unsigned sb) {
#pragma unroll
        for (int u = 0; u < 8; u++) {
            const int i = u*256 + tid;
            const int mat = i >> 9, row = (i >> 3) & 63, c8 = i & 7;
            const __half* src = (mat==0 ? g_Kh : mat==1 ? g_Kl : mat==2 ? g_Vh : g_Vl)
                              + kbase + (size_t)(kt*64 + row)*HDdim + c8*8;
            cp_async16(sb + mat*(64*FPITCH_B) + row*FPITCH_B + c8*16, src);
        }
        asm volatile("cp.async.commit_group;");
    };
    load_kv(0, sKV);   // one group: Q chunks + KV tile 0

    asm volatile("cp.async.wait_group 0;");
    __syncthreads();

    // Q A-fragments, loaded once; afterwards the Q region becomes KV stage 1
    unsigned qh[4][4], ql[4][4];
    {
        const unsigned aoff = (unsigned)(wm + (lane & 15))*FPITCH_B + ((lane >> 4) << 3)*2;
#pragma unroll
        for (int kf = 0; kf < 4; kf++) {
            ldmat_x4(qh[kf][0], qh[kf][1], qh[kf][2], qh[kf][3], sQ + aoff + kf*32);
            ldmat_x4(ql[kf][0], ql[kf][1], ql[kf][2], ql[kf][3],
                     sQ + 128*FPITCH_B + aoff + kf*32);
        }
    }
    __syncthreads();               // all warps done reading Q region
    load_kv(1, sQ);                // prefetch tile 1 into the freed Q region

    float acc[8][4] = {};
    unsigned o16[8][2] = {};       // f16x2 cross-term accumulators (Ph*Vl)
    float mr0 = -1e30f, mr1 = -1e30f, lr0 = 0.f, lr1 = 0.f;

    for (int kt = 0; kt < NTILES; kt++) {
        if (kt) {
            asm volatile("cp.async.wait_group 0;");
            __syncthreads();
            if (kt + 1 < NTILES) load_kv(kt + 1, (kt & 1) ? sKV : sQ);
        }
        const unsigned kb = (kt & 1) ? sQ : sKV;

        // ---- S = Q @ K^T  (3 products) ----
        float s[8][4] = {};
        {
            const int krow = ((lane >> 4) & 1)*8 + (lane & 7);
            const int ksel = ((lane >> 3) & 1)*8;
#pragma unroll
            for (int kf = 0; kf < 4; kf++) {
                const unsigned coff = (unsigned)(kf*16 + ksel)*2;
#pragma unroll
                for (int np = 0; np < 4; np++) {
                    unsigned bhf[4], blf[4];
                    const unsigned ad = kb + (unsigned)(np*16 + krow)*FPITCH_B + coff;
                    ldmat_x4(bhf[0], bhf[1], bhf[2], bhf[3], ad);
                    ldmat_x4(blf[0], blf[1], blf[2], blf[3], ad + 64*FPITCH_B);
                    mma_f16(s[2*np],   qh[kf], &bhf[0]);
                    mma_f16(s[2*np+1], qh[kf], &bhf[2]);
                    mma_f16(s[2*np],   qh[kf], &blf[0]);
                    mma_f16(s[2*np+1], qh[kf], &blf[2]);
                    mma_f16(s[2*np],   ql[kf], &bhf[0]);
                    mma_f16(s[2*np+1], ql[kf], &bhf[2]);
                }
            }
        }

        // ---- online softmax ----
#pragma unroll
        for (int rh = 0; rh < 2; rh++) {
            const int i0 = rh*2;
            float mx = fmaxf(s[0][i0], s[0][i0+1]);
#pragma unroll
            for (int nf = 1; nf < 8; nf++)
                mx = fmaxf(mx, fmaxf(s[nf][i0], s[nf][i0+1]));
            mx = fmaxf(mx, __shfl_xor_sync(0xffffffffu, mx, 1));
            mx = fmaxf(mx, __shfl_xor_sync(0xffffffffu, mx, 2));
            const float mold = rh ? mr1 : mr0;
            const float mnew = fmaxf(mold, mx);
            const float alpha = __expf(mold - mnew);
            float rs = 0.f;
#pragma unroll
            for (int nf = 0; nf < 8; nf++) {
                s[nf][i0]   = __expf(s[nf][i0]   - mnew);
                s[nf][i0+1] = __expf(s[nf][i0+1] - mnew);
                rs += s[nf][i0] + s[nf][i0+1];
            }
            rs += __shfl_xor_sync(0xffffffffu, rs, 1);
            rs += __shfl_xor_sync(0xffffffffu, rs, 2);
            if (rh) { lr1 = lr1*alpha + rs; mr1 = mnew; }
            else    { lr0 = lr0*alpha + rs; mr0 = mnew; }
            // rescale f32 accum + f16 cross accum for this row half
            const __half2 ha2 = __float2half2_rn(alpha);
            const unsigned hau = *reinterpret_cast<const unsigned*>(&ha2);
#pragma unroll
            for (int nf = 0; nf < 8; nf++) {
                acc[nf][i0]   *= alpha;
                acc[nf][i0+1] *= alpha;
                o16[nf][rh] = hmul2u(o16[nf][rh], hau);
            }
        }

        // ---- P -> fp16 A-fragments (hi only) ----
        unsigned pa[4][4];
#pragma unroll
        for (int kf = 0; kf < 4; kf++) {
            pa[kf][0] = pack_h(s[2*kf][0],   s[2*kf][1]);
            pa[kf][1] = pack_h(s[2*kf][2],   s[2*kf][3]);
            pa[kf][2] = pack_h(s[2*kf+1][0], s[2*kf+1][1]);
            pa[kf][3] = pack_h(s[2*kf+1][2], s[2*kf+1][3]);
        }

        // ---- O += P @ V: Ph*Vh (f32 acc) + Ph*Vl (f16 acc) ----
        {
            const int vrow = lane & 15;
            const int vsel = ((lane >> 4) & 1)*8;
#pragma unroll
            for (int kf = 0; kf < 4; kf++) {
#pragma unroll
                for (int np = 0; np < 4; np++) {
                    unsigned vhf[4], vlf[4];
                    const unsigned ad = kb + 2*(64*FPITCH_B)
                        + (unsigned)(kf*16 + vrow)*FPITCH_B + (np*16 + vsel)*2;
                    ldmat_x4_t(vhf[0], vhf[1], vhf[2], vhf[3], ad);
                    ldmat_x4_t(vlf[0], vlf[1], vlf[2], vlf[3], ad + 64*FPITCH_B);
                    mma_f16(acc[2*np],   pa[kf], &vhf[0]);
                    mma_f16(acc[2*np+1], pa[kf], &vhf[2]);
                    // cross term: f16 accumulators. o16[nf][0] covers acc[nf][0..1]
                    // (rows g), o16[nf][1] covers acc[nf][2..3] (rows g+8).
                    {
                        unsigned ctmp0[2] = { o16[2*np][0],   o16[2*np][1] };
                        unsigned ctmp1[2] = { o16[2*np+1][0], o16[2*np+1][1] };
                        mma_f16acc(ctmp0, pa[kf], &vlf[0]);
                        mma_f16acc(ctmp1, pa[kf], &vlf[2]);
                        o16[2*np][0] = ctmp0[0];   o16[2*np][1] = ctmp0[1];
                        o16[2*np+1][0] = ctmp1[0]; o16[2*np+1][1] = ctmp1[1];
                    }
                }
            }
        }
    }

    // epilogue -> bf16 (hi,lo) ctx split at g_ah[0]/g_al[0], layout [s*B+b][E]
    const int b = bh >> 4, hh = bh & 15;
    const int g = lane >> 2, tig = lane & 3;
    const float inv0 = 1.0f / lr0, inv1 = 1.0f / lr1;
    const int sg = q0 + wm + g;
#pragma unroll
    for (int nf = 0; nf < 8; nf++) {
        const int d = nf*8 + tig*2;
        const size_t i0 = ((size_t)sg*Bdim + b)*Edim + hh*HDdim + d;
        const size_t i1 = ((size_t)(sg+8)*Bdim + b)*Edim + hh*HDdim + d;
        const __half2 x0 = *reinterpret_cast<const __half2*>(&o16[nf][0]);
        const __half2 x1 = *reinterpret_cast<const __half2*>(&o16[nf][1]);
        unsigned lo0, lo1;
        const unsigned hi0 = pack_bf((acc[nf][0] + __low2float(x0))*inv0,
                                     (acc[nf][1] + __high2float(x0))*inv0, lo0);
        const unsigned hi1 = pack_bf((acc[nf][2] + __low2float(x1))*inv1,
                                     (acc[nf][3] + __high2float(x1))*inv1, lo1);
        *(unsigned*)(&g_ah[0][i0]) = hi0;
        *(unsigned*)(&g_al[0][i0]) = lo0;
        *(unsigned*)(&g_ah[0][i1]) = hi1;
        *(unsigned*)(&g_al[0][i1]) = lo1;
    }
}

// ---------------- launch ----------------
extern "C" void kernel_launch(void* const* d_in, const int* in_sizes, int n_in,
                              void* d_out, int out_size) {
    const float* query = (const float*)d_in[0];
    const float* key_  = (const float*)d_in[1];
    const float* value = (const float*)d_in[2];
    const float* Wq = (const float*)d_in[3];
    const float* bq = (const float*)d_in[4];
    const float* Wk = (const float*)d_in[5];
    const float* bk = (const float*)d_in[6];
    const float* Wv = (const float*)d_in[7];
    const float* bv = (const float*)d_in[8];
    const float* Wo = (const float*)d_in[9];
    const float* bo = (const float*)d_in[10];
    float* out = (float*)d_out;

    static bool attr_set = false;
    if (!attr_set) {
        cudaFuncSetAttribute(flash_tc, cudaFuncAttributeMaxDynamicSharedMemorySize, FL_SMEM);
        cudaFuncSetAttribute(gemm_tc<0>, cudaFuncAttributeMaxDynamicSharedMemorySize, GEMM_SMEM);
        cudaFuncSetAttribute(gemm_tc<1>, cudaFuncAttributeMaxDynamicSharedMemorySize, GEMM_SMEM);
        attr_set = true;
    }

    const unsigned nsplit = (unsigned)((3*NAELEM + 4*NBELEM) / 1024);   // 16384
    split_all<<<nsplit, 256>>>(query, key_, value, Wq, Wk, Wv, Wo);

    gemm_tc<0><<<dim3(Edim/128, Mrows/128, 3), 256, GEMM_SMEM>>>(bq, bk, bv, nullptr);

    flash_tc<<<dim3(Sdim/128, Bdim*Hn), 256, FL_SMEM>>>();

    gemm_tc<1><<<dim3(Edim/128, Mrows/128), 256, GEMM_SMEM>>>(bo, nullptr, nullptr, out);
}

// round 16
// speedup vs baseline: 1.0959x; 1.0930x over previous
#include <cuda_runtime.h>
#include <cuda_bf16.h>
#include <cuda_fp16.h>

#define Sdim 2048
#define Bdim 2
#define Edim 1024
#define Hn   16
#define HDdim 64
#define Mrows (Sdim*Bdim)   // 4096 token rows
#define NAELEM ((size_t)Mrows*Edim)   // 4M
#define NBELEM ((size_t)Edim*Edim)    // 1M

// ---------------- scratch (device globals: allocation-free) ----------------
// fp16 split QKV (written by projection epilogues), layout [b*H+h][s][d]
#define QKV_ELEMS ((size_t)Bdim*Hn*Sdim*HDdim)
__device__ __align__(16) __half g_Qh[QKV_ELEMS];
__device__ __align__(16) __half g_Ql[QKV_ELEMS];
__device__ __align__(16) __half g_Kh[QKV_ELEMS];
__device__ __align__(16) __half g_Kl[QKV_ELEMS];
__device__ __align__(16) __half g_Vh[QKV_ELEMS];
__device__ __align__(16) __half g_Vl[QKV_ELEMS];

// fp16 split A operands: [0]=query (later reused for ctx hi), [1]=key, [2]=value
__device__ __align__(16) __half g_ah[3][NAELEM];
__device__ __align__(16) __half g_al[3][NAELEM];
// fp16 split weights: 0=Wq 1=Wk 2=Wv 3=Wo
__device__ __align__(16) __half g_bh[4][NBELEM];
__device__ __align__(16) __half g_bl[4][NBELEM];

// ---------------- split helpers (fp16 hi/lo) ----------------
__device__ __forceinline__ void split1h(float x, __half& h, __half& l) {
    h = __float2half_rn(x);
    l = __float2half_rn(x - __half2float(h));
}
__device__ __forceinline__ void split4h(const float4 v, __half* hi, __half* lo) {
    __half h0,h1,h2,h3,l0,l1,l2,l3;
    split1h(v.x,h0,l0); split1h(v.y,h1,l1); split1h(v.z,h2,l2); split1h(v.w,h3,l3);
    __half2* ph = (__half2*)hi;
    ph[0] = __halves2half2(h0,h1); ph[1] = __halves2half2(h2,h3);
    __half2* pl = (__half2*)lo;
    pl[0] = __halves2half2(l0,l1); pl[1] = __halves2half2(l2,l3);
}

// One launch covers inputs (3 x 4M) then weights (4 x 1M).
__global__ __launch_bounds__(256) void split_all(const float* __restrict__ q,
                                                 const float* __restrict__ k,
                                                 const float* __restrict__ v,
                                                 const float* __restrict__ wq,
                                                 const float* __restrict__ wk,
                                                 const float* __restrict__ wv,
                                                 const float* __restrict__ wo) {
    const size_t i = ((size_t)blockIdx.x * blockDim.x + threadIdx.x) * 4;
    if (i < 3*NAELEM) {
        const int t = (int)(i >> 22);              // NAELEM = 2^22
        const size_t off = i & (NAELEM - 1);
        const float* x = (t == 0) ? q : (t == 1) ? k : v;
        split4h(*(const float4*)(x + off), &g_ah[t][off], &g_al[t][off]);
    } else {
        const size_t j = i - 3*NAELEM;
        const int t = (int)(j >> 20);              // NBELEM = 2^20
        const size_t off = j & (NBELEM - 1);
        const float* x = (t == 0) ? wq : (t == 1) ? wk : (t == 2) ? wv : wo;
        split4h(*(const float4*)(x + off), &g_bh[t][off], &g_bl[t][off]);
    }
}

// ---------------- mma helpers ----------------
__device__ __forceinline__ void ldmat_x4(unsigned& r0, unsigned& r1, unsigned& r2,
                                         unsigned& r3, unsigned addr) {
    asm volatile("ldmatrix.sync.aligned.m8n8.x4.shared.b16 {%0,%1,%2,%3}, [%4];"
                 : "=r"(r0), "=r"(r1), "=r"(r2), "=r"(r3) : "r"(addr));
}
__device__ __forceinline__ void ldmat_x4_t(unsigned& r0, unsigned& r1, unsigned& r2,
                                           unsigned& r3, unsigned addr) {
    asm volatile("ldmatrix.sync.aligned.m8n8.x4.trans.shared.b16 {%0,%1,%2,%3}, [%4];"
                 : "=r"(r0), "=r"(r1), "=r"(r2), "=r"(r3) : "r"(addr));
}
__device__ __forceinline__ void ldmat_x2(unsigned& r0, unsigned& r1, unsigned addr) {
    asm volatile("ldmatrix.sync.aligned.m8n8.x2.shared.b16 {%0,%1}, [%2];"
                 : "=r"(r0), "=r"(r1) : "r"(addr));
}
__device__ __forceinline__ void mma_f16(float* c, const unsigned* a, const unsigned* b) {
    asm volatile(
        "mma.sync.aligned.m16n8k16.row.col.f32.f16.f16.f32 "
        "{%0,%1,%2,%3}, {%4,%5,%6,%7}, {%8,%9}, {%0,%1,%2,%3};"
        : "+f"(c[0]), "+f"(c[1]), "+f"(c[2]), "+f"(c[3])
        : "r"(a[0]), "r"(a[1]), "r"(a[2]), "r"(a[3]), "r"(b[0]), "r"(b[1]));
}
__device__ __forceinline__ void cp_async16(unsigned saddr, const void* gaddr) {
    asm volatile("cp.async.cg.shared.global [%0], [%1], 16;" :: "r"(saddr), "l"(gaddr));
}
__device__ __forceinline__ unsigned pack_hl(float x, float y, unsigned& lo) {
    __half hx = __float2half_rn(x), hy = __float2half_rn(y);
    __half lx = __float2half_rn(x - __half2float(hx));
    __half ly = __float2half_rn(y - __half2float(hy));
    lo = ((unsigned)__half_as_ushort(ly) << 16) | (unsigned)__half_as_ushort(lx);
    return ((unsigned)__half_as_ushort(hy) << 16) | (unsigned)__half_as_ushort(hx);
}
__device__ __forceinline__ unsigned pack_h(float x, float y) {
    __half hx = __float2half_rn(x), hy = __float2half_rn(y);
    return ((unsigned)__half_as_ushort(hy) << 16) | (unsigned)__half_as_ushort(hx);
}

// ---------------- tensor-core GEMM: C[4096,1024] = A @ B^T + bias ----------------
// 128x128 CTA tile, 8 warps (2m x 4n), K-block 32, 2-stage cp.async, 2 CTAs/SM.
// fp16 split products. Q,K (MODE 0, z<2): 3 products AhBh+AhBl+AlBh.
// V (z==2) and out-proj (MODE 1): 2 products Ah(Bh+Bl) — Al never loaded.
// MODE 0: fused QKV (epilogue -> fp16 hi/lo head-major)
// MODE 1: output projection (ctx hi @ g_ah[0] x Wo split; epilogue -> fp32 out)
#define PITCH 40
#define KBLK  32
#define MAT_BYTES (128*PITCH*2)
#define STAGE_BYTES (4*MAT_BYTES)       // 40960
#define GEMM_SMEM (2*STAGE_BYTES)       // 81920 -> 2 CTAs/SM
#define NKB (Edim/KBLK)                 // 32

template<int MODE>
__global__ __launch_bounds__(256, 2) void gemm_tc(const float* __restrict__ bias0,
                                                  const float* __restrict__ bias1,
                                                  const float* __restrict__ bias2,
                                                  float* __restrict__ out) {
    extern __shared__ char smc[];
    const unsigned sbase = (unsigned)__cvta_generic_to_shared(smc);
    const int tid = threadIdx.x, lane = tid & 31, wid = tid >> 5;
    const int m0 = blockIdx.y << 7, n0 = blockIdx.x << 7;
    const int z = (MODE == 0) ? blockIdx.z : 0;
    const bool use_al = (MODE == 0) && (z < 2);
    const int wm = (wid & 1) << 6;
    const int wn = (wid >> 1) << 5;

    const __half* Ah = (MODE == 0) ? g_ah[z] : g_ah[0];
    const __half* Al = (MODE == 0) ? g_al[z] : g_al[0];
    const __half* Bh = (MODE == 0) ? g_bh[z] : g_bh[3];
    const __half* Bl = (MODE == 0) ? g_bl[z] : g_bl[3];
    const float* bias = (MODE == 1) ? bias0
                       : (z == 0) ? bias0 : (z == 1) ? bias1 : bias2;

    unsigned soff[8]; const __half* gp[8];
#pragma unroll
    for (int u = 0; u < 8; u++) {
        const int i = u*256 + tid;
        const int mat = i >> 9;
        const int row = (i >> 2) & 127, c4 = i & 3;
        soff[u] = mat*MAT_BYTES + row*(PITCH*2) + c4*16;
        const __half* src = (mat==0) ? Ah : (mat==1) ? Al : (mat==2) ? Bh : Bl;
        const size_t r = (mat < 2) ? (size_t)(m0 + row) : (size_t)(n0 + row);
        gp[u] = src + r*Edim + c4*8;
    }
    auto load_stage = [&](int kb) {
        const unsigned sb = sbase + (kb & 1)*STAGE_BYTES;
#pragma unroll
        for (int u = 0; u < 8; u++) {
            // u==1 is the Al matrix chunk (mat = (u*256+tid)>>9 == 1 exactly for u==1..?)
            // mat layout: i in [512,1024) -> mat 1. With 256 threads, u=2,3 are... recompute:
            // i = u*256+tid: mat = i>>9 -> u=0,1 -> mat0(A hi) for i<512; u=2,3 -> mat1(Al);
            // u=4,5 -> mat2(Bh); u=6,7 -> mat3(Bl).
            if (!use_al && (u == 2 || u == 3)) continue;   // skip Al load
            cp_async16(sb + soff[u], gp[u] + kb*KBLK);
        }
        asm volatile("cp.async.commit_group;");
    };

    float c[4][4][4] = {};
    load_stage(0);

    for (int kb = 0; kb < NKB; kb++) {
        asm volatile("cp.async.wait_group 0;");   // stage kb resident
        __syncthreads();                          // prior compute done with other stage
        if (kb + 1 < NKB) load_stage(kb + 1);     // overlaps compute below

        const unsigned sAh = sbase + (kb & 1)*STAGE_BYTES;
        const unsigned sAl = sAh + MAT_BYTES;
        const unsigned sBh = sAh + 2*MAT_BYTES;
        const unsigned sBl = sAh + 3*MAT_BYTES;
        const int arow = wm + (lane & 15);
        const int akof = (lane >> 4) << 3;
        const int brow = wn + (lane & 7);
        const int bkof = ((lane >> 3) & 1) << 3;

#pragma unroll
        for (int ks = 0; ks < 2; ks++) {
            const int k0 = ks << 4;
            unsigned ah[4][4], al[4][4], b[4][2];
#pragma unroll
            for (int mf = 0; mf < 4; mf++) {
                const unsigned off = (unsigned)(arow + mf*16)*(PITCH*2) + (k0 + akof)*2;
                ldmat_x4(ah[mf][0], ah[mf][1], ah[mf][2], ah[mf][3], sAh + off);
                if (use_al)
                    ldmat_x4(al[mf][0], al[mf][1], al[mf][2], al[mf][3], sAl + off);
            }
#pragma unroll
            for (int nf = 0; nf < 4; nf++) {
                const unsigned off = (unsigned)(brow + nf*8)*(PITCH*2) + (k0 + bkof)*2;
                ldmat_x2(b[nf][0], b[nf][1], sBh + off);
            }
#pragma unroll
            for (int mf = 0; mf < 4; mf++)
#pragma unroll
                for (int nf = 0; nf < 4; nf++) {
                    mma_f16(c[mf][nf], ah[mf], b[nf]);
                    if (use_al) mma_f16(c[mf][nf], al[mf], b[nf]);
                }
#pragma unroll
            for (int nf = 0; nf < 4; nf++) {
                const unsigned off = (unsigned)(brow + nf*8)*(PITCH*2) + (k0 + bkof)*2;
                ldmat_x2(b[nf][0], b[nf][1], sBl + off);
            }
#pragma unroll
            for (int mf = 0; mf < 4; mf++)
#pragma unroll
                for (int nf = 0; nf < 4; nf++)
                    mma_f16(c[mf][nf], ah[mf], b[nf]);
        }
    }

    // epilogue
    const int g = lane >> 2, tig = lane & 3;
#pragma unroll
    for (int mf = 0; mf < 4; mf++) {
#pragma unroll
        for (int nf = 0; nf < 4; nf++) {
            const int col = n0 + wn + nf*8 + tig*2;
            const float2 bb = *(const float2*)(bias + col);
#pragma unroll
            for (int half = 0; half < 2; half++) {
                const int m = m0 + wm + mf*16 + g + half*8;
                float2 o;
                o.x = c[mf][nf][half*2+0] + bb.x;
                o.y = c[mf][nf][half*2+1] + bb.y;
                if (MODE == 1) {
                    *(float2*)(out + (size_t)m * Edim + col) = o;
                } else {
                    const int s = m >> 1, b2 = m & 1;   // m = s*B + b
                    const int hh = col >> 6, d2 = col & 63;
                    const size_t idx = ((size_t)(b2*Hn + hh) * Sdim + s) * HDdim + d2;
                    unsigned lo;
                    const unsigned hi = pack_hl(o.x, o.y, lo);
                    __half* dh = (z == 0) ? g_Qh : (z == 1) ? g_Kh : g_Vh;
                    __half* dl = (z == 0) ? g_Ql : (z == 1) ? g_Kl : g_Vl;
                    *(unsigned*)(dh + idx) = hi;
                    *(unsigned*)(dl + idx) = lo;
                }
            }
        }
    }
}

// ---------------- tensor-core flash attention ----------------
// BLOCK_M=128 (8 warps x m16), BLOCK_N=64 keys/tile, HD=64.
// QK = QhKh + QhKl + QlKh (3 products); PV = PhVh + PhVl (2 products).
// KV stage 1 overlays the Q smem region -> 72KB smem, 2 CTAs/SM.
// Epilogue writes fp16 HI-ONLY ctx into g_ah[0] (out-proj is 2-product).
#define FPITCH_B 144
#define QSM_BYTES (2*128*FPITCH_B)      // 36864 (also stage-1 KV region)
#define KSTAGE_BYTES (4*64*FPITCH_B)    // 36864
#define FL_SMEM (QSM_BYTES + KSTAGE_BYTES)   // 73728
#define NTILES (Sdim/64)

__global__ __launch_bounds__(256, 2) void flash_tc() {
    extern __shared__ char smc[];
    const unsigned sbase = (unsigned)__cvta_generic_to_shared(smc);
    const unsigned sQ = sbase;                    // Q region; later KV stage 1
    const unsigned sKV = sbase + QSM_BYTES;       // KV stage 0
    const int tid = threadIdx.x, lane = tid & 31, wid = tid >> 5;
    const int bh = blockIdx.y;
    const int q0 = blockIdx.x << 7;
    const int wm = wid << 4;

    const size_t qbase = ((size_t)bh * Sdim + q0) * HDdim;
    const size_t kbase = (size_t)bh * Sdim * HDdim;

#pragma unroll
    for (int u = 0; u < 8; u++) {
        const int i = u*256 + tid;
        const int mat = i >> 10, row = (i >> 3) & 127, c8 = i & 7;
        const __half* src = (mat ? g_Ql : g_Qh) + qbase + (size_t)row*HDdim + c8*8;
        cp_async16(sQ + mat*(128*FPITCH_B) + row*FPITCH_B + c8*16, src);
    }
    auto load_kv = [&](int kt, unsigned sb) {
#pragma unroll
        for (int u = 0; u < 8; u++) {
            const int i = u*256 + tid;
            const int mat = i >> 9, row = (i >> 3) & 63, c8 = i & 7;
            const __half* src = (mat==0 ? g_Kh : mat==1 ? g_Kl : mat==2 ? g_Vh : g_Vl)
                              + kbase + (size_t)(kt*64 + row)*HDdim + c8*8;
            cp_async16(sb + mat*(64*FPITCH_B) + row*FPITCH_B + c8*16, src);
        }
        asm volatile("cp.async.commit_group;");
    };
    load_kv(0, sKV);   // one group: Q chunks + KV tile 0

    asm volatile("cp.async.wait_group 0;");
    __syncthreads();

    // Q A-fragments, loaded once; afterwards the Q region becomes KV stage 1
    unsigned qh[4][4], ql[4][4];
    {
        const unsigned aoff = (unsigned)(wm + (lane & 15))*FPITCH_B + ((lane >> 4) << 3)*2;
#pragma unroll
        for (int kf = 0; kf < 4; kf++) {
            ldmat_x4(qh[kf][0], qh[kf][1], qh[kf][2], qh[kf][3], sQ + aoff + kf*32);
            ldmat_x4(ql[kf][0], ql[kf][1], ql[kf][2], ql[kf][3],
                     sQ + 128*FPITCH_B + aoff + kf*32);
        }
    }
    __syncthreads();               // all warps done reading Q region
    load_kv(1, sQ);                // prefetch tile 1 into the freed Q region

    float acc[8][4] = {};
    float mr0 = -1e30f, mr1 = -1e30f, lr0 = 0.f, lr1 = 0.f;

    for (int kt = 0; kt < NTILES; kt++) {
        if (kt) {
            asm volatile("cp.async.wait_group 0;");
            __syncthreads();
            if (kt + 1 < NTILES) load_kv(kt + 1, (kt & 1) ? sKV : sQ);
        }
        const unsigned kb = (kt & 1) ? sQ : sKV;

        // ---- S = Q @ K^T  (3 products) ----
        float s[8][4] = {};
        {
            const int krow = ((lane >> 4) & 1)*8 + (lane & 7);
            const int ksel = ((lane >> 3) & 1)*8;
#pragma unroll
            for (int kf = 0; kf < 4; kf++) {
                const unsigned coff = (unsigned)(kf*16 + ksel)*2;
#pragma unroll
                for (int np = 0; np < 4; np++) {
                    unsigned bhf[4], blf[4];
                    const unsigned ad = kb + (unsigned)(np*16 + krow)*FPITCH_B + coff;
                    ldmat_x4(bhf[0], bhf[1], bhf[2], bhf[3], ad);
                    ldmat_x4(blf[0], blf[1], blf[2], blf[3], ad + 64*FPITCH_B);
                    mma_f16(s[2*np],   qh[kf], &bhf[0]);
                    mma_f16(s[2*np+1], qh[kf], &bhf[2]);
                    mma_f16(s[2*np],   qh[kf], &blf[0]);
                    mma_f16(s[2*np+1], qh[kf], &blf[2]);
                    mma_f16(s[2*np],   ql[kf], &bhf[0]);
                    mma_f16(s[2*np+1], ql[kf], &bhf[2]);
                }
            }
        }

        // ---- online softmax ----
#pragma unroll
        for (int rh = 0; rh < 2; rh++) {
            const int i0 = rh*2;
            float mx = fmaxf(s[0][i0], s[0][i0+1]);
#pragma unroll
            for (int nf = 1; nf < 8; nf++)
                mx = fmaxf(mx, fmaxf(s[nf][i0], s[nf][i0+1]));
            mx = fmaxf(mx, __shfl_xor_sync(0xffffffffu, mx, 1));
            mx = fmaxf(mx, __shfl_xor_sync(0xffffffffu, mx, 2));
            const float mold = rh ? mr1 : mr0;
            const float mnew = fmaxf(mold, mx);
            const float alpha = __expf(mold - mnew);
            float rs = 0.f;
#pragma unroll
            for (int nf = 0; nf < 8; nf++) {
                s[nf][i0]   = __expf(s[nf][i0]   - mnew);
                s[nf][i0+1] = __expf(s[nf][i0+1] - mnew);
                rs += s[nf][i0] + s[nf][i0+1];
            }
            rs += __shfl_xor_sync(0xffffffffu, rs, 1);
            rs += __shfl_xor_sync(0xffffffffu, rs, 2);
            if (rh) { lr1 = lr1*alpha + rs; mr1 = mnew; }
            else    { lr0 = lr0*alpha + rs; mr0 = mnew; }
#pragma unroll
            for (int nf = 0; nf < 8; nf++) {
                acc[nf][i0]   *= alpha;
                acc[nf][i0+1] *= alpha;
            }
        }

        // ---- P -> fp16 A-fragments (hi only; lo term dropped, ~1e-4 residual) ----
        unsigned pa[4][4];
#pragma unroll
        for (int kf = 0; kf < 4; kf++) {
            pa[kf][0] = pack_h(s[2*kf][0],   s[2*kf][1]);
            pa[kf][1] = pack_h(s[2*kf][2],   s[2*kf][3]);
            pa[kf][2] = pack_h(s[2*kf+1][0], s[2*kf+1][1]);
            pa[kf][3] = pack_h(s[2*kf+1][2], s[2*kf+1][3]);
        }

        // ---- O += P @ V  (2 products: Ph*Vh + Ph*Vl) ----
        {
            const int vrow = lane & 15;
            const int vsel = ((lane >> 4) & 1)*8;
#pragma unroll
            for (int kf = 0; kf < 4; kf++) {
#pragma unroll
                for (int np = 0; np < 4; np++) {
                    unsigned vhf[4], vlf[4];
                    const unsigned ad = kb + 2*(64*FPITCH_B)
                        + (unsigned)(kf*16 + vrow)*FPITCH_B + (np*16 + vsel)*2;
                    ldmat_x4_t(vhf[0], vhf[1], vhf[2], vhf[3], ad);
                    ldmat_x4_t(vlf[0], vlf[1], vlf[2], vlf[3], ad + 64*FPITCH_B);
                    mma_f16(acc[2*np],   pa[kf], &vhf[0]);
                    mma_f16(acc[2*np+1], pa[kf], &vhf[2]);
                    mma_f16(acc[2*np],   pa[kf], &vlf[0]);
                    mma_f16(acc[2*np+1], pa[kf], &vlf[2]);
                }
            }
        }
    }

    // epilogue -> fp16 HI ctx at g_ah[0], layout [s*B+b][E] (out-proj is 2-product)
    const int b = bh >> 4, hh = bh & 15;
    const int g = lane >> 2, tig = lane & 3;
    const float inv0 = 1.0f / lr0, inv1 = 1.0f / lr1;
    const int sg = q0 + wm + g;
#pragma unroll
    for (int nf = 0; nf < 8; nf++) {
        const int d = nf*8 + tig*2;
        const size_t i0 = ((size_t)sg*Bdim + b)*Edim + hh*HDdim + d;
        const size_t i1 = ((size_t)(sg+8)*Bdim + b)*Edim + hh*HDdim + d;
        *(unsigned*)(&g_ah[0][i0]) = pack_h(acc[nf][0]*inv0, acc[nf][1]*inv0);
        *(unsigned*)(&g_ah[0][i1]) = pack_h(acc[nf][2]*inv1, acc[nf][3]*inv1);
    }
}

// ---------------- launch ----------------
extern "C" void kernel_launch(void* const* d_in, const int* in_sizes, int n_in,
                              void* d_out, int out_size) {
    const float* query = (const float*)d_in[0];
    const float* key_  = (const float*)d_in[1];
    const float* value = (const float*)d_in[2];
    const float* Wq = (const float*)d_in[3];
    const float* bq = (const float*)d_in[4];
    const float* Wk = (const float*)d_in[5];
    const float* bk = (const float*)d_in[6];
    const float* Wv = (const float*)d_in[7];
    const float* bv = (const float*)d_in[8];
    const float* Wo = (const float*)d_in[9];
    const float* bo = (const float*)d_in[10];
    float* out = (float*)d_out;

    static bool attr_set = false;
    if (!attr_set) {
        cudaFuncSetAttribute(flash_tc, cudaFuncAttributeMaxDynamicSharedMemorySize, FL_SMEM);
        cudaFuncSetAttribute(gemm_tc<0>, cudaFuncAttributeMaxDynamicSharedMemorySize, GEMM_SMEM);
        cudaFuncSetAttribute(gemm_tc<1>, cudaFuncAttributeMaxDynamicSharedMemorySize, GEMM_SMEM);
        attr_set = true;
    }

    const unsigned nsplit = (unsigned)((3*NAELEM + 4*NBELEM) / 1024);   // 16384
    split_all<<<nsplit, 256>>>(query, key_, value, Wq, Wk, Wv, Wo);

    gemm_tc<0><<<dim3(Edim/128, Mrows/128, 3), 256, GEMM_SMEM>>>(bq, bk, bv, nullptr);

    flash_tc<<<dim3(Sdim/128, Bdim*Hn), 256, FL_SMEM>>>();

    gemm_tc<1><<<dim3(Edim/128, Mrows/128), 256, GEMM_SMEM>>>(bo, nullptr, nullptr, out);
}